// round 15
// baseline (speedup 1.0000x reference)
#include <cuda_runtime.h>
#include <cuda_bf16.h>
#include <cuda_fp16.h>
#include <cuda_fp8.h>
#include <cstdint>

// ============================================================================
// Problem constants
// ============================================================================
#define NROWS 16384
#define DDIM  256
#define INV_T 14.285714285714286f        // 1 / 0.07
// y = sim*INV_T*log2(e) - SHIFT2 ; sim = acc/64 -> y = acc*K2 - SHIFT2
#define K2F    0.32203014f               // INV_T*log2e/64
#define SHIFT2 9.0f
#define SHIFT2_LN2 6.23832462504f        // 9*ln(2)

// SMEM tile geometry: fp8, 256 B/row padded to 272 B
#define STRIDE_B 272
#define TILE_BYTES (128 * STRIDE_B)      // 34816 per 128x256 fp8 tile
#define SMEM_DYN_BYTES (2 * TILE_BYTES)  // A + B = 69632 -> 3 CTAs/SM

// phase stagger: cycles per phase step (breaks co-resident CTA lockstep)
#define STAGGER_CYC 1600ull

// ============================================================================
// Device scratch
// ============================================================================
__device__ uint8_t g_V8[(size_t)NROWS * DDIM];  // normalized img * 8, e4m3
__device__ uint8_t g_U8[(size_t)NROWS * DDIM];  // normalized txt * 8, e4m3
__device__ float g_rowsum[NROWS];
__device__ float g_colsum[NROWS];
__device__ float g_diag[NROWS];

// ============================================================================
// PTX helpers (baseline sm_89 features -> legal under compute_103)
// ============================================================================
__device__ __forceinline__ uint32_t smem_u32(const void* p) {
    uint32_t a;
    asm("{ .reg .u64 t; cvta.to.shared.u64 t, %1; cvt.u32.u64 %0, t; }"
        : "=r"(a) : "l"(p));
    return a;
}

#define CP_ASYNC16(dst_u32, src_ptr) \
    asm volatile("cp.async.cg.shared.global [%0], [%1], 16;" \
        :: "r"(dst_u32), "l"(src_ptr) : "memory")
#define CP_ASYNC_COMMIT() asm volatile("cp.async.commit_group;" ::: "memory")
#define CP_ASYNC_WAIT_0() asm volatile("cp.async.wait_group 0;" ::: "memory")

__device__ __forceinline__ void ldsm4(uint32_t* r, uint32_t addr) {
    asm volatile("ldmatrix.sync.aligned.m8n8.x4.shared.b16 {%0,%1,%2,%3}, [%4];"
        : "=r"(r[0]), "=r"(r[1]), "=r"(r[2]), "=r"(r[3]) : "r"(addr));
}

// fp8 e4m3 MMA with f16 accumulators
__device__ __forceinline__ void mma_fp8_f16(uint32_t* c, const uint32_t* a, const uint32_t* b) {
    asm volatile(
        "mma.sync.aligned.m16n8k32.row.col.f16.e4m3.e4m3.f16 "
        "{%0,%1}, {%2,%3,%4,%5}, {%6,%7}, {%0,%1};"
        : "+r"(c[0]), "+r"(c[1])
        : "r"(a[0]), "r"(a[1]), "r"(a[2]), "r"(a[3]), "r"(b[0]), "r"(b[1]));
}

__device__ __forceinline__ uint32_t h2exp2(uint32_t y) {
    uint32_t e;
    asm("ex2.approx.f16x2 %0, %1;" : "=r"(e) : "r"(y));
    return e;
}
__device__ __forceinline__ uint32_t h2fma(uint32_t x, uint32_t k, uint32_t b) {
    uint32_t d;
    asm("fma.rn.f16x2 %0, %1, %2, %3;" : "=r"(d) : "r"(x), "r"(k), "r"(b));
    return d;
}
__device__ __forceinline__ uint32_t h2add(uint32_t x, uint32_t y) {
    uint32_t d;
    asm("add.rn.f16x2 %0, %1, %2;" : "=r"(d) : "r"(x), "r"(y));
    return d;
}
__device__ __forceinline__ float h2low(uint32_t h) {
    __half2 v = *reinterpret_cast<__half2*>(&h);
    return __low2float(v);
}
__device__ __forceinline__ float h2high(uint32_t h) {
    __half2 v = *reinterpret_cast<__half2*>(&h);
    return __high2float(v);
}

// ============================================================================
// Kernel A: per-row L2 normalize -> (8*v) as e4m3, diag cos, zero accums
// ============================================================================
__global__ __launch_bounds__(256) void normalize_kernel(
    const float* __restrict__ img, const float* __restrict__ txt)
{
    int warp = threadIdx.x >> 5, lane = threadIdx.x & 31;
    int row = blockIdx.x * 8 + warp;

    const float4* v4 = reinterpret_cast<const float4*>(img) + (size_t)row * (DDIM / 4) + lane * 2;
    const float4* u4 = reinterpret_cast<const float4*>(txt) + (size_t)row * (DDIM / 4) + lane * 2;
    float4 a0 = v4[0], a1 = v4[1];
    float4 b0 = u4[0], b1 = u4[1];

    float sv = a0.x*a0.x + a0.y*a0.y + a0.z*a0.z + a0.w*a0.w
             + a1.x*a1.x + a1.y*a1.y + a1.z*a1.z + a1.w*a1.w;
    float su = b0.x*b0.x + b0.y*b0.y + b0.z*b0.z + b0.w*b0.w
             + b1.x*b1.x + b1.y*b1.y + b1.z*b1.z + b1.w*b1.w;
    float dv = a0.x*b0.x + a0.y*b0.y + a0.z*b0.z + a0.w*b0.w
             + a1.x*b1.x + a1.y*b1.y + a1.z*b1.z + a1.w*b1.w;

    #pragma unroll
    for (int s = 16; s > 0; s >>= 1) {
        sv += __shfl_xor_sync(0xffffffffu, sv, s);
        su += __shfl_xor_sync(0xffffffffu, su, s);
        dv += __shfl_xor_sync(0xffffffffu, dv, s);
    }

    float nv = fmaxf(sqrtf(sv), 1e-8f);
    float nu = fmaxf(sqrtf(su), 1e-8f);
    float inv_v = 8.0f / nv;
    float inv_u = 8.0f / nu;

    if (lane == 0) {
        g_diag[row]   = dv / (nv * nu);
        g_rowsum[row] = 0.0f;
        g_colsum[row] = 0.0f;
    }

    uint32_t w0, w1;
    {
        __nv_fp8x2_storage_t p0 = __nv_cvt_float2_to_fp8x2(
            make_float2(a0.x*inv_v, a0.y*inv_v), __NV_SATFINITE, __NV_E4M3);
        __nv_fp8x2_storage_t p1 = __nv_cvt_float2_to_fp8x2(
            make_float2(a0.z*inv_v, a0.w*inv_v), __NV_SATFINITE, __NV_E4M3);
        __nv_fp8x2_storage_t p2 = __nv_cvt_float2_to_fp8x2(
            make_float2(a1.x*inv_v, a1.y*inv_v), __NV_SATFINITE, __NV_E4M3);
        __nv_fp8x2_storage_t p3 = __nv_cvt_float2_to_fp8x2(
            make_float2(a1.z*inv_v, a1.w*inv_v), __NV_SATFINITE, __NV_E4M3);
        w0 = (uint32_t)p0 | ((uint32_t)p1 << 16);
        w1 = (uint32_t)p2 | ((uint32_t)p3 << 16);
    }
    reinterpret_cast<uint2*>(g_V8)[(size_t)row * (DDIM / 8) + lane] = make_uint2(w0, w1);

    {
        __nv_fp8x2_storage_t q0 = __nv_cvt_float2_to_fp8x2(
            make_float2(b0.x*inv_u, b0.y*inv_u), __NV_SATFINITE, __NV_E4M3);
        __nv_fp8x2_storage_t q1 = __nv_cvt_float2_to_fp8x2(
            make_float2(b0.z*inv_u, b0.w*inv_u), __NV_SATFINITE, __NV_E4M3);
        __nv_fp8x2_storage_t q2 = __nv_cvt_float2_to_fp8x2(
            make_float2(b1.x*inv_u, b1.y*inv_u), __NV_SATFINITE, __NV_E4M3);
        __nv_fp8x2_storage_t q3 = __nv_cvt_float2_to_fp8x2(
            make_float2(b1.z*inv_u, b1.w*inv_u), __NV_SATFINITE, __NV_E4M3);
        w0 = (uint32_t)q0 | ((uint32_t)q1 << 16);
        w1 = (uint32_t)q2 | ((uint32_t)q3 << 16);
    }
    reinterpret_cast<uint2*>(g_U8)[(size_t)row * (DDIM / 8) + lane] = make_uint2(w0, w1);
}

// ============================================================================
// Kernel B: fused fp8 GEMM, f16 acc. 128x128 item per CTA, 128 threads,
// 4 warps of 64x64 tiles (2x2), 3 CTAs/SM (R13 champion) + phase stagger:
// (bid % 3) * 1600cyc start delay breaks co-resident CTA lockstep so one
// CTA's load wait hides under the other two CTAs' MMA bursts.
// ============================================================================
__global__ __launch_bounds__(128, 3) void simloss_mma_kernel()
{
    extern __shared__ __align__(16) char smbuf[];

    int tid = threadIdx.x, lane = tid & 31, wid = tid >> 5;
    int warp_m = wid & 1, warp_n = wid >> 1;   // 2x2 grid of 64x64 warp tiles
    int bm = blockIdx.y;        // row-tile (V rows)
    int bx = blockIdx.x;        // column-tile (U rows)

    // ---- phase stagger: co-resident CTAs have bids ~148/296 apart; 148%3=1
    // so the three slots get distinct delays {0, 1600, 3200} cycles. ----
    {
        int bidf = blockIdx.y * gridDim.x + blockIdx.x;
        int ph = bidf - (bidf / 3) * 3;
        if (ph) {
            uint64_t lim = (uint64_t)ph * STAGGER_CYC;
            uint64_t t0 = clock64();
            while (clock64() - t0 < lim) {}
        }
    }

    // ---- async loads: A + B, one group ----
    const char* Ag = reinterpret_cast<const char*>(g_V8) + (size_t)bm * 128 * DDIM;
    const char* Bg = reinterpret_cast<const char*>(g_U8) + (size_t)bx * 128 * DDIM;
    uint32_t As_u = smem_u32(smbuf);
    uint32_t Bs_u = As_u + TILE_BYTES;

    #pragma unroll
    for (int it = 0; it < 16; it++) {
        int i = it * 128 + tid;           // 2048 16B segments per tile
        int row = i >> 4, c = i & 15;
        uint32_t soff = row * STRIDE_B + c * 16;
        uint32_t goff = row * 256 + c * 16;
        CP_ASYNC16(As_u + soff, Ag + goff);
        CP_ASYNC16(Bs_u + soff, Bg + goff);
    }
    CP_ASYNC_COMMIT();

    // ldmatrix per-lane addresses
    uint32_t a_base = As_u + (warp_m * 64 + (lane & 15)) * STRIDE_B + (lane >> 4) * 16;
    uint32_t b_base = Bs_u +
        (warp_n * 64 + (lane & 7) + ((lane >> 4) << 3)) * STRIDE_B + ((lane >> 3) & 1) * 16;

    // acc: [mt(4)*8+nt(8)][2] f16x2 regs (64 total)
    uint32_t acc[64];
    #pragma unroll
    for (int i = 0; i < 64; i++) acc[i] = 0u;

    CP_ASYNC_WAIT_0();
    __syncthreads();

    // ---- mainloop: K = 256 = 8 k-steps of 32 ----
    #pragma unroll
    for (int ks = 0; ks < 8; ks++) {
        uint32_t a[4][4];
        #pragma unroll
        for (int mt = 0; mt < 4; mt++)
            ldsm4(a[mt], a_base + ks * 32 + mt * 16 * STRIDE_B);
        uint32_t b[4][4];
        #pragma unroll
        for (int p = 0; p < 4; p++)
            ldsm4(b[p], b_base + ks * 32 + p * 16 * STRIDE_B);
        #pragma unroll
        for (int mt = 0; mt < 4; mt++)
            #pragma unroll
            for (int p = 0; p < 4; p++) {
                mma_fp8_f16(&acc[(mt * 8 + 2 * p) * 2],     a[mt], &b[p][0]);
                mma_fp8_f16(&acc[(mt * 8 + 2 * p + 1) * 2], a[mt], &b[p][2]);
            }
    }

    // ---- epilogue: y = acc*K2 - 9 ; e = 2^y ; fp16x2 sums ----
    __half2 hk = __half2half2(__float2half_rn(K2F));
    __half2 hs = __half2half2(__float2half_rn(-SHIFT2));
    uint32_t K2u = *reinterpret_cast<uint32_t*>(&hk);
    uint32_t S2u = *reinterpret_cast<uint32_t*>(&hs);

    uint32_t rpa[4] = {0u, 0u, 0u, 0u};   // rows (16mt+g)
    uint32_t rpb[4] = {0u, 0u, 0u, 0u};   // rows (16mt+8+g)
    uint32_t cph[8];                       // [nt]: (col 2u, 2u+1) over 8 rows
    #pragma unroll
    for (int i = 0; i < 8; i++) cph[i] = 0u;

    #pragma unroll
    for (int mt = 0; mt < 4; mt++)
        #pragma unroll
        for (int nt = 0; nt < 8; nt++) {
            int idx = (mt * 8 + nt) * 2;
            uint32_t e0 = h2exp2(h2fma(acc[idx],     K2u, S2u));  // row 16mt+g
            uint32_t e1 = h2exp2(h2fma(acc[idx + 1], K2u, S2u));  // row 16mt+8+g
            rpa[mt] = h2add(rpa[mt], e0);
            rpb[mt] = h2add(rpb[mt], e1);
            cph[nt] = h2add(cph[nt], h2add(e0, e1));
        }

    // row reduce across the 4 u-lanes
    #pragma unroll
    for (int s = 1; s <= 2; s <<= 1) {
        #pragma unroll
        for (int mt = 0; mt < 4; mt++) {
            rpa[mt] = h2add(rpa[mt], __shfl_xor_sync(0xffffffffu, rpa[mt], s));
            rpb[mt] = h2add(rpb[mt], __shfl_xor_sync(0xffffffffu, rpb[mt], s));
        }
    }
    if ((lane & 3) == 0) {
        int g = lane >> 2;
        #pragma unroll
        for (int mt = 0; mt < 4; mt++) {
            int r = bm * 128 + warp_m * 64 + mt * 16 + g;
            atomicAdd(&g_rowsum[r],     h2low(rpa[mt]) + h2high(rpa[mt]));
            atomicAdd(&g_rowsum[r + 8], h2low(rpb[mt]) + h2high(rpb[mt]));
        }
    }

    // col reduce across the 8 g-groups
    #pragma unroll
    for (int s = 4; s <= 16; s <<= 1)
        #pragma unroll
        for (int i = 0; i < 8; i++)
            cph[i] = h2add(cph[i], __shfl_xor_sync(0xffffffffu, cph[i], s));
    if (lane < 4) {
        int u = lane;
        #pragma unroll
        for (int nt = 0; nt < 8; nt++) {
            int cb = bx * 128 + warp_n * 64 + nt * 8 + 2 * u;
            atomicAdd(&g_colsum[cb],     h2low(cph[nt]));
            atomicAdd(&g_colsum[cb + 1], h2high(cph[nt]));
        }
    }
}

// ============================================================================
// Kernel C: finalize. loss = 9ln2 + mean(log sum) - (1/T)*mean(diag)
// ============================================================================
__global__ __launch_bounds__(256) void finalize_kernel(float* __restrict__ out)
{
    __shared__ float red_lv[8], red_lu[8], red_d[8];
    int tid = threadIdx.x, lane = tid & 31, warp = tid >> 5;

    float slv = 0.0f, slu = 0.0f, sd = 0.0f;
    for (int i = tid; i < NROWS; i += 256) {
        slv += logf(g_rowsum[i]);
        slu += logf(g_colsum[i]);
        sd  += g_diag[i];
    }
    #pragma unroll
    for (int s = 16; s > 0; s >>= 1) {
        slv += __shfl_xor_sync(0xffffffffu, slv, s);
        slu += __shfl_xor_sync(0xffffffffu, slu, s);
        sd  += __shfl_xor_sync(0xffffffffu, sd,  s);
    }
    if (lane == 0) { red_lv[warp] = slv; red_lu[warp] = slu; red_d[warp] = sd; }
    __syncthreads();
    if (tid == 0) {
        float tlv = 0.0f, tlu = 0.0f, td = 0.0f;
        #pragma unroll
        for (int w = 0; w < 8; w++) { tlv += red_lv[w]; tlu += red_lu[w]; td += red_d[w]; }
        float mlv = tlv * (1.0f / NROWS);
        float mlu = tlu * (1.0f / NROWS);
        float md  = td  * (1.0f / NROWS);
        float loss_vu = SHIFT2_LN2 + mlv - INV_T * md;
        float loss_uv = SHIFT2_LN2 + mlu - INV_T * md;
        out[0] = 0.5f * loss_vu + 0.5f * loss_uv;
        out[1] = loss_vu;
        out[2] = loss_uv;
    }
}

// ============================================================================
// Launch
// ============================================================================
extern "C" void kernel_launch(void* const* d_in, const int* in_sizes, int n_in,
                              void* d_out, int out_size)
{
    const float* img = (const float*)d_in[0];
    const float* txt = (const float*)d_in[1];
    float* out = (float*)d_out;

    cudaFuncSetAttribute(simloss_mma_kernel,
                         cudaFuncAttributeMaxDynamicSharedMemorySize, SMEM_DYN_BYTES);

    normalize_kernel<<<NROWS / 8, 256>>>(img, txt);
    simloss_mma_kernel<<<dim3(NROWS / 128, NROWS / 128), 128, SMEM_DYN_BYTES>>>();
    finalize_kernel<<<1, 256>>>(out);
}

// round 16
// speedup vs baseline: 1.0445x; 1.0445x over previous
#include <cuda_runtime.h>
#include <cuda_bf16.h>
#include <cuda_fp16.h>
#include <cuda_fp8.h>
#include <cstdint>

// ============================================================================
// Problem constants
// ============================================================================
#define NROWS 16384
#define DDIM  256
#define INV_T 14.285714285714286f        // 1 / 0.07
// y = sim*INV_T*log2(e) - SHIFT2 ; sim = acc/64 -> y = acc*K2 - SHIFT2
#define K2F    0.32203014f               // INV_T*log2e/64
#define SHIFT2 9.0f
#define SHIFT2_LN2 6.23832462504f        // 9*ln(2)

// SMEM tile geometry: fp8, 256 B/row padded to 272 B
#define STRIDE_B 272
#define TILE_BYTES (128 * STRIDE_B)      // 34816 per 128x256 fp8 tile
#define SMEM_DYN_BYTES (2 * TILE_BYTES)  // A + B = 69632 -> 3 CTAs/SM

// ============================================================================
// Device scratch
// ============================================================================
__device__ uint8_t g_V8[(size_t)NROWS * DDIM];  // normalized img * 8, e4m3
__device__ uint8_t g_U8[(size_t)NROWS * DDIM];  // normalized txt * 8, e4m3
__device__ float g_rowsum[NROWS];
__device__ float g_colsum[NROWS];
__device__ float g_diag[NROWS];

// ============================================================================
// PTX helpers (baseline sm_89 features -> legal under compute_103)
// ============================================================================
__device__ __forceinline__ uint32_t smem_u32(const void* p) {
    uint32_t a;
    asm("{ .reg .u64 t; cvta.to.shared.u64 t, %1; cvt.u32.u64 %0, t; }"
        : "=r"(a) : "l"(p));
    return a;
}

#define CP_ASYNC16(dst_u32, src_ptr) \
    asm volatile("cp.async.cg.shared.global [%0], [%1], 16;" \
        :: "r"(dst_u32), "l"(src_ptr) : "memory")
#define CP_ASYNC_COMMIT() asm volatile("cp.async.commit_group;" ::: "memory")
#define CP_ASYNC_WAIT_0() asm volatile("cp.async.wait_group 0;" ::: "memory")

__device__ __forceinline__ void ldsm4(uint32_t* r, uint32_t addr) {
    asm volatile("ldmatrix.sync.aligned.m8n8.x4.shared.b16 {%0,%1,%2,%3}, [%4];"
        : "=r"(r[0]), "=r"(r[1]), "=r"(r[2]), "=r"(r[3]) : "r"(addr));
}

// fp8 e4m3 MMA with f16 accumulators
__device__ __forceinline__ void mma_fp8_f16(uint32_t* c, const uint32_t* a, const uint32_t* b) {
    asm volatile(
        "mma.sync.aligned.m16n8k32.row.col.f16.e4m3.e4m3.f16 "
        "{%0,%1}, {%2,%3,%4,%5}, {%6,%7}, {%0,%1};"
        : "+r"(c[0]), "+r"(c[1])
        : "r"(a[0]), "r"(a[1]), "r"(a[2]), "r"(a[3]), "r"(b[0]), "r"(b[1]));
}

__device__ __forceinline__ uint32_t h2exp2(uint32_t y) {
    uint32_t e;
    asm("ex2.approx.f16x2 %0, %1;" : "=r"(e) : "r"(y));
    return e;
}
__device__ __forceinline__ uint32_t h2fma(uint32_t x, uint32_t k, uint32_t b) {
    uint32_t d;
    asm("fma.rn.f16x2 %0, %1, %2, %3;" : "=r"(d) : "r"(x), "r"(k), "r"(b));
    return d;
}
__device__ __forceinline__ uint32_t h2add(uint32_t x, uint32_t y) {
    uint32_t d;
    asm("add.rn.f16x2 %0, %1, %2;" : "=r"(d) : "r"(x), "r"(y));
    return d;
}
__device__ __forceinline__ float h2low(uint32_t h) {
    __half2 v = *reinterpret_cast<__half2*>(&h);
    return __low2float(v);
}
__device__ __forceinline__ float h2high(uint32_t h) {
    __half2 v = *reinterpret_cast<__half2*>(&h);
    return __high2float(v);
}

// ============================================================================
// Kernel A: per-row L2 normalize -> (8*v) as e4m3, diag cos, zero accums
// ============================================================================
__global__ __launch_bounds__(256) void normalize_kernel(
    const float* __restrict__ img, const float* __restrict__ txt)
{
    int warp = threadIdx.x >> 5, lane = threadIdx.x & 31;
    int row = blockIdx.x * 8 + warp;

    const float4* v4 = reinterpret_cast<const float4*>(img) + (size_t)row * (DDIM / 4) + lane * 2;
    const float4* u4 = reinterpret_cast<const float4*>(txt) + (size_t)row * (DDIM / 4) + lane * 2;
    float4 a0 = v4[0], a1 = v4[1];
    float4 b0 = u4[0], b1 = u4[1];

    float sv = a0.x*a0.x + a0.y*a0.y + a0.z*a0.z + a0.w*a0.w
             + a1.x*a1.x + a1.y*a1.y + a1.z*a1.z + a1.w*a1.w;
    float su = b0.x*b0.x + b0.y*b0.y + b0.z*b0.z + b0.w*b0.w
             + b1.x*b1.x + b1.y*b1.y + b1.z*b1.z + b1.w*b1.w;
    float dv = a0.x*b0.x + a0.y*b0.y + a0.z*b0.z + a0.w*b0.w
             + a1.x*b1.x + a1.y*b1.y + a1.z*b1.z + a1.w*b1.w;

    #pragma unroll
    for (int s = 16; s > 0; s >>= 1) {
        sv += __shfl_xor_sync(0xffffffffu, sv, s);
        su += __shfl_xor_sync(0xffffffffu, su, s);
        dv += __shfl_xor_sync(0xffffffffu, dv, s);
    }

    float nv = fmaxf(sqrtf(sv), 1e-8f);
    float nu = fmaxf(sqrtf(su), 1e-8f);
    float inv_v = 8.0f / nv;
    float inv_u = 8.0f / nu;

    if (lane == 0) {
        g_diag[row]   = dv / (nv * nu);
        g_rowsum[row] = 0.0f;
        g_colsum[row] = 0.0f;
    }

    uint32_t w0, w1;
    {
        __nv_fp8x2_storage_t p0 = __nv_cvt_float2_to_fp8x2(
            make_float2(a0.x*inv_v, a0.y*inv_v), __NV_SATFINITE, __NV_E4M3);
        __nv_fp8x2_storage_t p1 = __nv_cvt_float2_to_fp8x2(
            make_float2(a0.z*inv_v, a0.w*inv_v), __NV_SATFINITE, __NV_E4M3);
        __nv_fp8x2_storage_t p2 = __nv_cvt_float2_to_fp8x2(
            make_float2(a1.x*inv_v, a1.y*inv_v), __NV_SATFINITE, __NV_E4M3);
        __nv_fp8x2_storage_t p3 = __nv_cvt_float2_to_fp8x2(
            make_float2(a1.z*inv_v, a1.w*inv_v), __NV_SATFINITE, __NV_E4M3);
        w0 = (uint32_t)p0 | ((uint32_t)p1 << 16);
        w1 = (uint32_t)p2 | ((uint32_t)p3 << 16);
    }
    reinterpret_cast<uint2*>(g_V8)[(size_t)row * (DDIM / 8) + lane] = make_uint2(w0, w1);

    {
        __nv_fp8x2_storage_t q0 = __nv_cvt_float2_to_fp8x2(
            make_float2(b0.x*inv_u, b0.y*inv_u), __NV_SATFINITE, __NV_E4M3);
        __nv_fp8x2_storage_t q1 = __nv_cvt_float2_to_fp8x2(
            make_float2(b0.z*inv_u, b0.w*inv_u), __NV_SATFINITE, __NV_E4M3);
        __nv_fp8x2_storage_t q2 = __nv_cvt_float2_to_fp8x2(
            make_float2(b1.x*inv_u, b1.y*inv_u), __NV_SATFINITE, __NV_E4M3);
        __nv_fp8x2_storage_t q3 = __nv_cvt_float2_to_fp8x2(
            make_float2(b1.z*inv_u, b1.w*inv_u), __NV_SATFINITE, __NV_E4M3);
        w0 = (uint32_t)q0 | ((uint32_t)q1 << 16);
        w1 = (uint32_t)q2 | ((uint32_t)q3 << 16);
    }
    reinterpret_cast<uint2*>(g_U8)[(size_t)row * (DDIM / 8) + lane] = make_uint2(w0, w1);
}

// ============================================================================
// Kernel B: fused fp8 GEMM, f16 acc. 128x128 item per CTA, 128 threads,
// 4 warps of 64x64 tiles (2x2), 3 CTAs/SM (R13) + explicit double-buffered
// fragments: k+1's LDSMs issue before k's MMAs, guaranteeing the ldsm
// latency hides under 32 MMAs regardless of ptxas hoisting.
// ============================================================================
__global__ __launch_bounds__(128, 3) void simloss_mma_kernel()
{
    extern __shared__ __align__(16) char smbuf[];

    int tid = threadIdx.x, lane = tid & 31, wid = tid >> 5;
    int warp_m = wid & 1, warp_n = wid >> 1;   // 2x2 grid of 64x64 warp tiles
    int bm = blockIdx.y;        // row-tile (V rows)
    int bx = blockIdx.x;        // column-tile (U rows)

    // ---- async loads: A + B, one group ----
    const char* Ag = reinterpret_cast<const char*>(g_V8) + (size_t)bm * 128 * DDIM;
    const char* Bg = reinterpret_cast<const char*>(g_U8) + (size_t)bx * 128 * DDIM;
    uint32_t As_u = smem_u32(smbuf);
    uint32_t Bs_u = As_u + TILE_BYTES;

    #pragma unroll
    for (int it = 0; it < 16; it++) {
        int i = it * 128 + tid;           // 2048 16B segments per tile
        int row = i >> 4, c = i & 15;
        uint32_t soff = row * STRIDE_B + c * 16;
        uint32_t goff = row * 256 + c * 16;
        CP_ASYNC16(As_u + soff, Ag + goff);
        CP_ASYNC16(Bs_u + soff, Bg + goff);
    }
    CP_ASYNC_COMMIT();

    // ldmatrix per-lane addresses
    uint32_t a_base = As_u + (warp_m * 64 + (lane & 15)) * STRIDE_B + (lane >> 4) * 16;
    uint32_t b_base = Bs_u +
        (warp_n * 64 + (lane & 7) + ((lane >> 4) << 3)) * STRIDE_B + ((lane >> 3) & 1) * 16;

    // acc: [mt(4)*8+nt(8)][2] f16x2 regs (64 total)
    uint32_t acc[64];
    #pragma unroll
    for (int i = 0; i < 64; i++) acc[i] = 0u;

    CP_ASYNC_WAIT_0();
    __syncthreads();

    // ---- mainloop: K = 256 = 8 k-steps of 32; double-buffered fragments ----
    uint32_t a[2][4][4], b[2][4][4];

    // preload k-step 0 into buffer 0
    #pragma unroll
    for (int mt = 0; mt < 4; mt++)
        ldsm4(a[0][mt], a_base + mt * 16 * STRIDE_B);
    #pragma unroll
    for (int p = 0; p < 4; p++)
        ldsm4(b[0][p], b_base + p * 16 * STRIDE_B);

    #pragma unroll
    for (int ks = 0; ks < 8; ks++) {
        int cur = ks & 1, nxt = cur ^ 1;

        // issue k+1's loads BEFORE k's MMAs (hidden under 32 MMAs)
        if (ks < 7) {
            #pragma unroll
            for (int mt = 0; mt < 4; mt++)
                ldsm4(a[nxt][mt], a_base + (ks + 1) * 32 + mt * 16 * STRIDE_B);
            #pragma unroll
            for (int p = 0; p < 4; p++)
                ldsm4(b[nxt][p], b_base + (ks + 1) * 32 + p * 16 * STRIDE_B);
        }

        #pragma unroll
        for (int mt = 0; mt < 4; mt++)
            #pragma unroll
            for (int p = 0; p < 4; p++) {
                mma_fp8_f16(&acc[(mt * 8 + 2 * p) * 2],     a[cur][mt], &b[cur][p][0]);
                mma_fp8_f16(&acc[(mt * 8 + 2 * p + 1) * 2], a[cur][mt], &b[cur][p][2]);
            }
    }

    // ---- epilogue: y = acc*K2 - 9 ; e = 2^y ; fp16x2 sums ----
    __half2 hk = __half2half2(__float2half_rn(K2F));
    __half2 hs = __half2half2(__float2half_rn(-SHIFT2));
    uint32_t K2u = *reinterpret_cast<uint32_t*>(&hk);
    uint32_t S2u = *reinterpret_cast<uint32_t*>(&hs);

    uint32_t rpa[4] = {0u, 0u, 0u, 0u};   // rows (16mt+g)
    uint32_t rpb[4] = {0u, 0u, 0u, 0u};   // rows (16mt+8+g)
    uint32_t cph[8];                       // [nt]: (col 2u, 2u+1) over 8 rows
    #pragma unroll
    for (int i = 0; i < 8; i++) cph[i] = 0u;

    #pragma unroll
    for (int mt = 0; mt < 4; mt++)
        #pragma unroll
        for (int nt = 0; nt < 8; nt++) {
            int idx = (mt * 8 + nt) * 2;
            uint32_t e0 = h2exp2(h2fma(acc[idx],     K2u, S2u));  // row 16mt+g
            uint32_t e1 = h2exp2(h2fma(acc[idx + 1], K2u, S2u));  // row 16mt+8+g
            rpa[mt] = h2add(rpa[mt], e0);
            rpb[mt] = h2add(rpb[mt], e1);
            cph[nt] = h2add(cph[nt], h2add(e0, e1));
        }

    // row reduce across the 4 u-lanes
    #pragma unroll
    for (int s = 1; s <= 2; s <<= 1) {
        #pragma unroll
        for (int mt = 0; mt < 4; mt++) {
            rpa[mt] = h2add(rpa[mt], __shfl_xor_sync(0xffffffffu, rpa[mt], s));
            rpb[mt] = h2add(rpb[mt], __shfl_xor_sync(0xffffffffu, rpb[mt], s));
        }
    }
    if ((lane & 3) == 0) {
        int g = lane >> 2;
        #pragma unroll
        for (int mt = 0; mt < 4; mt++) {
            int r = bm * 128 + warp_m * 64 + mt * 16 + g;
            atomicAdd(&g_rowsum[r],     h2low(rpa[mt]) + h2high(rpa[mt]));
            atomicAdd(&g_rowsum[r + 8], h2low(rpb[mt]) + h2high(rpb[mt]));
        }
    }

    // col reduce across the 8 g-groups
    #pragma unroll
    for (int s = 4; s <= 16; s <<= 1)
        #pragma unroll
        for (int i = 0; i < 8; i++)
            cph[i] = h2add(cph[i], __shfl_xor_sync(0xffffffffu, cph[i], s));
    if (lane < 4) {
        int u = lane;
        #pragma unroll
        for (int nt = 0; nt < 8; nt++) {
            int cb = bx * 128 + warp_n * 64 + nt * 8 + 2 * u;
            atomicAdd(&g_colsum[cb],     h2low(cph[nt]));
            atomicAdd(&g_colsum[cb + 1], h2high(cph[nt]));
        }
    }
}

// ============================================================================
// Kernel C: finalize. loss = 9ln2 + mean(log sum) - (1/T)*mean(diag)
// ============================================================================
__global__ __launch_bounds__(256) void finalize_kernel(float* __restrict__ out)
{
    __shared__ float red_lv[8], red_lu[8], red_d[8];
    int tid = threadIdx.x, lane = tid & 31, warp = tid >> 5;

    float slv = 0.0f, slu = 0.0f, sd = 0.0f;
    for (int i = tid; i < NROWS; i += 256) {
        slv += logf(g_rowsum[i]);
        slu += logf(g_colsum[i]);
        sd  += g_diag[i];
    }
    #pragma unroll
    for (int s = 16; s > 0; s >>= 1) {
        slv += __shfl_xor_sync(0xffffffffu, slv, s);
        slu += __shfl_xor_sync(0xffffffffu, slu, s);
        sd  += __shfl_xor_sync(0xffffffffu, sd,  s);
    }
    if (lane == 0) { red_lv[warp] = slv; red_lu[warp] = slu; red_d[warp] = sd; }
    __syncthreads();
    if (tid == 0) {
        float tlv = 0.0f, tlu = 0.0f, td = 0.0f;
        #pragma unroll
        for (int w = 0; w < 8; w++) { tlv += red_lv[w]; tlu += red_lu[w]; td += red_d[w]; }
        float mlv = tlv * (1.0f / NROWS);
        float mlu = tlu * (1.0f / NROWS);
        float md  = td  * (1.0f / NROWS);
        float loss_vu = SHIFT2_LN2 + mlv - INV_T * md;
        float loss_uv = SHIFT2_LN2 + mlu - INV_T * md;
        out[0] = 0.5f * loss_vu + 0.5f * loss_uv;
        out[1] = loss_vu;
        out[2] = loss_uv;
    }
}

// ============================================================================
// Launch
// ============================================================================
extern "C" void kernel_launch(void* const* d_in, const int* in_sizes, int n_in,
                              void* d_out, int out_size)
{
    const float* img = (const float*)d_in[0];
    const float* txt = (const float*)d_in[1];
    float* out = (float*)d_out;

    cudaFuncSetAttribute(simloss_mma_kernel,
                         cudaFuncAttributeMaxDynamicSharedMemorySize, SMEM_DYN_BYTES);

    normalize_kernel<<<NROWS / 8, 256>>>(img, txt);
    simloss_mma_kernel<<<dim3(NROWS / 128, NROWS / 128), 128, SMEM_DYN_BYTES>>>();
    finalize_kernel<<<1, 256>>>(out);
}

// round 17
// speedup vs baseline: 1.1079x; 1.0608x over previous
#include <cuda_runtime.h>
#include <cuda_bf16.h>
#include <cuda_fp16.h>
#include <cuda_fp8.h>
#include <cstdint>

// ============================================================================
// Problem constants
// ============================================================================
#define NROWS 16384
#define DDIM  256
#define INV_T 14.285714285714286f        // 1 / 0.07
// y = sim*INV_T*log2(e) - SHIFT2 ; sim = acc/64 -> y = acc*K2 - SHIFT2
#define K2F    0.32203014f               // INV_T*log2e/64
#define SHIFT2 9.0f
#define SHIFT2_LN2 6.23832462504f        // 9*ln(2)

// SMEM tile geometry: fp8, 256 B/row padded to 272 B
#define STRIDE_B 272
#define TILE_BYTES (128 * STRIDE_B)      // 34816 per 128x256 fp8 tile
#define SMEM_DYN_BYTES (2 * TILE_BYTES)  // A + B = 69632 -> 3 CTAs/SM

#define STAGGER_CYC 1600ull
#define FIRST_WAVE  444                  // 3 CTAs/SM x 148 SMs

#define FIN_BLOCKS 64

// ============================================================================
// Device scratch
// ============================================================================
__device__ uint8_t g_V8[(size_t)NROWS * DDIM];  // normalized img * 8, e4m3
__device__ uint8_t g_U8[(size_t)NROWS * DDIM];  // normalized txt * 8, e4m3
__device__ float g_rowsum[NROWS];
__device__ float g_colsum[NROWS];
__device__ float g_diag[NROWS];
__device__ float g_part[3];              // finalize staging: {sum log rs, sum log cs, sum diag}
__device__ unsigned int g_done;

// ============================================================================
// PTX helpers (baseline sm_89 features -> legal under compute_103)
// ============================================================================
__device__ __forceinline__ uint32_t smem_u32(const void* p) {
    uint32_t a;
    asm("{ .reg .u64 t; cvta.to.shared.u64 t, %1; cvt.u32.u64 %0, t; }"
        : "=r"(a) : "l"(p));
    return a;
}

#define CP_ASYNC16(dst_u32, src_ptr) \
    asm volatile("cp.async.cg.shared.global [%0], [%1], 16;" \
        :: "r"(dst_u32), "l"(src_ptr) : "memory")
#define CP_ASYNC_COMMIT() asm volatile("cp.async.commit_group;" ::: "memory")
#define CP_ASYNC_WAIT_0() asm volatile("cp.async.wait_group 0;" ::: "memory")

__device__ __forceinline__ void ldsm4(uint32_t* r, uint32_t addr) {
    asm volatile("ldmatrix.sync.aligned.m8n8.x4.shared.b16 {%0,%1,%2,%3}, [%4];"
        : "=r"(r[0]), "=r"(r[1]), "=r"(r[2]), "=r"(r[3]) : "r"(addr));
}

// fp8 e4m3 MMA with f16 accumulators
__device__ __forceinline__ void mma_fp8_f16(uint32_t* c, const uint32_t* a, const uint32_t* b) {
    asm volatile(
        "mma.sync.aligned.m16n8k32.row.col.f16.e4m3.e4m3.f16 "
        "{%0,%1}, {%2,%3,%4,%5}, {%6,%7}, {%0,%1};"
        : "+r"(c[0]), "+r"(c[1])
        : "r"(a[0]), "r"(a[1]), "r"(a[2]), "r"(a[3]), "r"(b[0]), "r"(b[1]));
}

__device__ __forceinline__ uint32_t h2exp2(uint32_t y) {
    uint32_t e;
    asm("ex2.approx.f16x2 %0, %1;" : "=r"(e) : "r"(y));
    return e;
}
__device__ __forceinline__ uint32_t h2fma(uint32_t x, uint32_t k, uint32_t b) {
    uint32_t d;
    asm("fma.rn.f16x2 %0, %1, %2, %3;" : "=r"(d) : "r"(x), "r"(k), "r"(b));
    return d;
}
__device__ __forceinline__ uint32_t h2add(uint32_t x, uint32_t y) {
    uint32_t d;
    asm("add.rn.f16x2 %0, %1, %2;" : "=r"(d) : "r"(x), "r"(y));
    return d;
}
__device__ __forceinline__ float h2low(uint32_t h) {
    __half2 v = *reinterpret_cast<__half2*>(&h);
    return __low2float(v);
}
__device__ __forceinline__ float h2high(uint32_t h) {
    __half2 v = *reinterpret_cast<__half2*>(&h);
    return __high2float(v);
}

// ============================================================================
// Kernel A: per-row L2 normalize -> (8*v) as e4m3, diag cos, zero accums
// ============================================================================
__global__ __launch_bounds__(256) void normalize_kernel(
    const float* __restrict__ img, const float* __restrict__ txt)
{
    if (blockIdx.x == 0 && threadIdx.x == 0) {
        g_part[0] = 0.0f; g_part[1] = 0.0f; g_part[2] = 0.0f;
        g_done = 0u;
    }

    int warp = threadIdx.x >> 5, lane = threadIdx.x & 31;
    int row = blockIdx.x * 8 + warp;

    const float4* v4 = reinterpret_cast<const float4*>(img) + (size_t)row * (DDIM / 4) + lane * 2;
    const float4* u4 = reinterpret_cast<const float4*>(txt) + (size_t)row * (DDIM / 4) + lane * 2;
    float4 a0 = v4[0], a1 = v4[1];
    float4 b0 = u4[0], b1 = u4[1];

    float sv = a0.x*a0.x + a0.y*a0.y + a0.z*a0.z + a0.w*a0.w
             + a1.x*a1.x + a1.y*a1.y + a1.z*a1.z + a1.w*a1.w;
    float su = b0.x*b0.x + b0.y*b0.y + b0.z*b0.z + b0.w*b0.w
             + b1.x*b1.x + b1.y*b1.y + b1.z*b1.z + b1.w*b1.w;
    float dv = a0.x*b0.x + a0.y*b0.y + a0.z*b0.z + a0.w*b0.w
             + a1.x*b1.x + a1.y*b1.y + a1.z*b1.z + a1.w*b1.w;

    #pragma unroll
    for (int s = 16; s > 0; s >>= 1) {
        sv += __shfl_xor_sync(0xffffffffu, sv, s);
        su += __shfl_xor_sync(0xffffffffu, su, s);
        dv += __shfl_xor_sync(0xffffffffu, dv, s);
    }

    float nv = fmaxf(sqrtf(sv), 1e-8f);
    float nu = fmaxf(sqrtf(su), 1e-8f);
    float inv_v = 8.0f / nv;
    float inv_u = 8.0f / nu;

    if (lane == 0) {
        g_diag[row]   = dv / (nv * nu);
        g_rowsum[row] = 0.0f;
        g_colsum[row] = 0.0f;
    }

    uint32_t w0, w1;
    {
        __nv_fp8x2_storage_t p0 = __nv_cvt_float2_to_fp8x2(
            make_float2(a0.x*inv_v, a0.y*inv_v), __NV_SATFINITE, __NV_E4M3);
        __nv_fp8x2_storage_t p1 = __nv_cvt_float2_to_fp8x2(
            make_float2(a0.z*inv_v, a0.w*inv_v), __NV_SATFINITE, __NV_E4M3);
        __nv_fp8x2_storage_t p2 = __nv_cvt_float2_to_fp8x2(
            make_float2(a1.x*inv_v, a1.y*inv_v), __NV_SATFINITE, __NV_E4M3);
        __nv_fp8x2_storage_t p3 = __nv_cvt_float2_to_fp8x2(
            make_float2(a1.z*inv_v, a1.w*inv_v), __NV_SATFINITE, __NV_E4M3);
        w0 = (uint32_t)p0 | ((uint32_t)p1 << 16);
        w1 = (uint32_t)p2 | ((uint32_t)p3 << 16);
    }
    reinterpret_cast<uint2*>(g_V8)[(size_t)row * (DDIM / 8) + lane] = make_uint2(w0, w1);

    {
        __nv_fp8x2_storage_t q0 = __nv_cvt_float2_to_fp8x2(
            make_float2(b0.x*inv_u, b0.y*inv_u), __NV_SATFINITE, __NV_E4M3);
        __nv_fp8x2_storage_t q1 = __nv_cvt_float2_to_fp8x2(
            make_float2(b0.z*inv_u, b0.w*inv_u), __NV_SATFINITE, __NV_E4M3);
        __nv_fp8x2_storage_t q2 = __nv_cvt_float2_to_fp8x2(
            make_float2(b1.x*inv_u, b1.y*inv_u), __NV_SATFINITE, __NV_E4M3);
        __nv_fp8x2_storage_t q3 = __nv_cvt_float2_to_fp8x2(
            make_float2(b1.z*inv_u, b1.w*inv_u), __NV_SATFINITE, __NV_E4M3);
        w0 = (uint32_t)q0 | ((uint32_t)q1 << 16);
        w1 = (uint32_t)q2 | ((uint32_t)q3 << 16);
    }
    reinterpret_cast<uint2*>(g_U8)[(size_t)row * (DDIM / 8) + lane] = make_uint2(w0, w1);
}

// ============================================================================
// Kernel B: fused fp8 GEMM, f16 acc. 128x128 item per CTA, 128 threads,
// 4 warps of 64x64 tiles (2x2), 3 CTAs/SM (R13 champion) + ONE-TIME phase
// stagger on the first wave only: replacement CTAs inherit the offset, so
// co-resident slots stay antiphase without re-paying the spin per item.
// ============================================================================
__global__ __launch_bounds__(128, 3) void simloss_mma_kernel()
{
    extern __shared__ __align__(16) char smbuf[];

    int tid = threadIdx.x, lane = tid & 31, wid = tid >> 5;
    int warp_m = wid & 1, warp_n = wid >> 1;   // 2x2 grid of 64x64 warp tiles
    int bm = blockIdx.y;        // row-tile (V rows)
    int bx = blockIdx.x;        // column-tile (U rows)

    // ---- one-time stagger (first wave only) ----
    {
        int bidf = blockIdx.y * gridDim.x + blockIdx.x;
        if (bidf < FIRST_WAVE) {
            int ph = bidf - (bidf / 3) * 3;
            if (ph) {
                uint64_t lim = (uint64_t)ph * STAGGER_CYC;
                uint64_t t0 = clock64();
                while (clock64() - t0 < lim) {}
            }
        }
    }

    // ---- async loads: A + B, one group ----
    const char* Ag = reinterpret_cast<const char*>(g_V8) + (size_t)bm * 128 * DDIM;
    const char* Bg = reinterpret_cast<const char*>(g_U8) + (size_t)bx * 128 * DDIM;
    uint32_t As_u = smem_u32(smbuf);
    uint32_t Bs_u = As_u + TILE_BYTES;

    #pragma unroll
    for (int it = 0; it < 16; it++) {
        int i = it * 128 + tid;           // 2048 16B segments per tile
        int row = i >> 4, c = i & 15;
        uint32_t soff = row * STRIDE_B + c * 16;
        uint32_t goff = row * 256 + c * 16;
        CP_ASYNC16(As_u + soff, Ag + goff);
        CP_ASYNC16(Bs_u + soff, Bg + goff);
    }
    CP_ASYNC_COMMIT();

    // ldmatrix per-lane addresses
    uint32_t a_base = As_u + (warp_m * 64 + (lane & 15)) * STRIDE_B + (lane >> 4) * 16;
    uint32_t b_base = Bs_u +
        (warp_n * 64 + (lane & 7) + ((lane >> 4) << 3)) * STRIDE_B + ((lane >> 3) & 1) * 16;

    // acc: [mt(4)*8+nt(8)][2] f16x2 regs (64 total)
    uint32_t acc[64];
    #pragma unroll
    for (int i = 0; i < 64; i++) acc[i] = 0u;

    CP_ASYNC_WAIT_0();
    __syncthreads();

    // ---- mainloop: K = 256 = 8 k-steps of 32 ----
    #pragma unroll
    for (int ks = 0; ks < 8; ks++) {
        uint32_t a[4][4];
        #pragma unroll
        for (int mt = 0; mt < 4; mt++)
            ldsm4(a[mt], a_base + ks * 32 + mt * 16 * STRIDE_B);
        uint32_t b[4][4];
        #pragma unroll
        for (int p = 0; p < 4; p++)
            ldsm4(b[p], b_base + ks * 32 + p * 16 * STRIDE_B);
        #pragma unroll
        for (int mt = 0; mt < 4; mt++)
            #pragma unroll
            for (int p = 0; p < 4; p++) {
                mma_fp8_f16(&acc[(mt * 8 + 2 * p) * 2],     a[mt], &b[p][0]);
                mma_fp8_f16(&acc[(mt * 8 + 2 * p + 1) * 2], a[mt], &b[p][2]);
            }
    }

    // ---- epilogue: y = acc*K2 - 9 ; e = 2^y ; fp16x2 sums ----
    __half2 hk = __half2half2(__float2half_rn(K2F));
    __half2 hs = __half2half2(__float2half_rn(-SHIFT2));
    uint32_t K2u = *reinterpret_cast<uint32_t*>(&hk);
    uint32_t S2u = *reinterpret_cast<uint32_t*>(&hs);

    uint32_t rpa[4] = {0u, 0u, 0u, 0u};   // rows (16mt+g)
    uint32_t rpb[4] = {0u, 0u, 0u, 0u};   // rows (16mt+8+g)
    uint32_t cph[8];                       // [nt]: (col 2u, 2u+1) over 8 rows
    #pragma unroll
    for (int i = 0; i < 8; i++) cph[i] = 0u;

    #pragma unroll
    for (int mt = 0; mt < 4; mt++)
        #pragma unroll
        for (int nt = 0; nt < 8; nt++) {
            int idx = (mt * 8 + nt) * 2;
            uint32_t e0 = h2exp2(h2fma(acc[idx],     K2u, S2u));  // row 16mt+g
            uint32_t e1 = h2exp2(h2fma(acc[idx + 1], K2u, S2u));  // row 16mt+8+g
            rpa[mt] = h2add(rpa[mt], e0);
            rpb[mt] = h2add(rpb[mt], e1);
            cph[nt] = h2add(cph[nt], h2add(e0, e1));
        }

    // row reduce across the 4 u-lanes
    #pragma unroll
    for (int s = 1; s <= 2; s <<= 1) {
        #pragma unroll
        for (int mt = 0; mt < 4; mt++) {
            rpa[mt] = h2add(rpa[mt], __shfl_xor_sync(0xffffffffu, rpa[mt], s));
            rpb[mt] = h2add(rpb[mt], __shfl_xor_sync(0xffffffffu, rpb[mt], s));
        }
    }
    if ((lane & 3) == 0) {
        int g = lane >> 2;
        #pragma unroll
        for (int mt = 0; mt < 4; mt++) {
            int r = bm * 128 + warp_m * 64 + mt * 16 + g;
            atomicAdd(&g_rowsum[r],     h2low(rpa[mt]) + h2high(rpa[mt]));
            atomicAdd(&g_rowsum[r + 8], h2low(rpb[mt]) + h2high(rpb[mt]));
        }
    }

    // col reduce across the 8 g-groups
    #pragma unroll
    for (int s = 4; s <= 16; s <<= 1)
        #pragma unroll
        for (int i = 0; i < 8; i++)
            cph[i] = h2add(cph[i], __shfl_xor_sync(0xffffffffu, cph[i], s));
    if (lane < 4) {
        int u = lane;
        #pragma unroll
        for (int nt = 0; nt < 8; nt++) {
            int cb = bx * 128 + warp_n * 64 + nt * 8 + 2 * u;
            atomicAdd(&g_colsum[cb],     h2low(cph[nt]));
            atomicAdd(&g_colsum[cb + 1], h2high(cph[nt]));
        }
    }
}

// ============================================================================
// Kernel C: parallel finalize. 64 CTAs reduce into g_part; last block writes
// out. loss = 9ln2 + mean(log sum) - (1/T)*mean(diag)
// ============================================================================
__global__ __launch_bounds__(256) void finalize_kernel(float* __restrict__ out)
{
    __shared__ float red_lv[8], red_lu[8], red_d[8];
    int tid = threadIdx.x, lane = tid & 31, warp = tid >> 5;

    float slv = 0.0f, slu = 0.0f, sd = 0.0f;
    for (int i = blockIdx.x * 256 + tid; i < NROWS; i += FIN_BLOCKS * 256) {
        slv += logf(g_rowsum[i]);
        slu += logf(g_colsum[i]);
        sd  += g_diag[i];
    }
    #pragma unroll
    for (int s = 16; s > 0; s >>= 1) {
        slv += __shfl_xor_sync(0xffffffffu, slv, s);
        slu += __shfl_xor_sync(0xffffffffu, slu, s);
        sd  += __shfl_xor_sync(0xffffffffu, sd,  s);
    }
    if (lane == 0) { red_lv[warp] = slv; red_lu[warp] = slu; red_d[warp] = sd; }
    __syncthreads();
    if (tid == 0) {
        float tlv = 0.0f, tlu = 0.0f, td = 0.0f;
        #pragma unroll
        for (int w = 0; w < 8; w++) { tlv += red_lv[w]; tlu += red_lu[w]; td += red_d[w]; }
        atomicAdd(&g_part[0], tlv);
        atomicAdd(&g_part[1], tlu);
        atomicAdd(&g_part[2], td);
        __threadfence();
        unsigned int t = atomicAdd(&g_done, 1u);
        if (t == FIN_BLOCKS - 1) {
            float mlv = g_part[0] * (1.0f / NROWS);
            float mlu = g_part[1] * (1.0f / NROWS);
            float md  = g_part[2] * (1.0f / NROWS);
            float loss_vu = SHIFT2_LN2 + mlv - INV_T * md;
            float loss_uv = SHIFT2_LN2 + mlu - INV_T * md;
            out[0] = 0.5f * loss_vu + 0.5f * loss_uv;
            out[1] = loss_vu;
            out[2] = loss_uv;
        }
    }
}

// ============================================================================
// Launch
// ============================================================================
extern "C" void kernel_launch(void* const* d_in, const int* in_sizes, int n_in,
                              void* d_out, int out_size)
{
    const float* img = (const float*)d_in[0];
    const float* txt = (const float*)d_in[1];
    float* out = (float*)d_out;

    cudaFuncSetAttribute(simloss_mma_kernel,
                         cudaFuncAttributeMaxDynamicSharedMemorySize, SMEM_DYN_BYTES);

    normalize_kernel<<<NROWS / 8, 256>>>(img, txt);
    simloss_mma_kernel<<<dim3(NROWS / 128, NROWS / 128), 128, SMEM_DYN_BYTES>>>();
    finalize_kernel<<<FIN_BLOCKS, 256>>>(out);
}